// round 4
// baseline (speedup 1.0000x reference)
#include <cuda_runtime.h>
#include <math.h>
#include <stdint.h>

#define R_N 1000
#define K_N 80
#define NCLS_P1 81
#define IMG_W_F 1333.0f
#define IMG_H_F 800.0f
#define CPC 100
#define OUT_COLS 87
#define CAP 1024
#define TB 512

typedef unsigned long long u64;
typedef unsigned int u32;

__device__ float g_psum[K_N];
__device__ float g_pmax[K_N];
__device__ u32 g_ord[K_N * CPC];   // per-class sorted kept scores (orderable), 0 = pad
__device__ int g_prop[K_N * CPC];  // original proposal row
__device__ int g_bar1 = 0;
__device__ int g_bar2 = 0;

__device__ __forceinline__ u32 ord32(float f) {
    u32 u = __float_as_uint(f);
    return (u & 0x80000000u) ? ~u : (u | 0x80000000u);
}

// key = ord<<32 | (79-c)<<7 | (99-k): ties break like flat top_k (smaller c, then k)
__device__ __forceinline__ u64 mkkey(u32 o, int c, int k) {
    return ((u64)o << 32) | (u32)(((K_N - 1 - c) << 7) | (CPC - 1 - k));
}

// merge pairs of sorted (desc) CPC-long u64 lists via per-element binary search.
// Keys are globally unique, so scatter positions are unique (race-free).
__device__ __forceinline__ void merge_lists(const u64* __restrict__ src,
                                            u64* __restrict__ dst, int n, int t) {
    int npair = n >> 1;
    int total = npair * (2 * CPC);
    for (int w = t; w < total; w += TB) {
        int p = w / (2 * CPC), e = w - p * (2 * CPC);
        const u64* X = src + (2 * p) * CPC;
        const u64* Y = X + CPC;
        u64 v; int base; const u64* other;
        if (e < CPC) { v = X[e];       base = e;       other = Y; }
        else         { v = Y[e - CPC]; base = e - CPC; other = X; }
        int lo = 0, hi = CPC;                 // count(other > v)
        while (lo < hi) { int mid = (lo + hi) >> 1; if (other[mid] > v) lo = mid + 1; else hi = mid; }
        int pos = base + lo;
        if (pos < CPC) dst[p * CPC + pos] = v;
    }
    if (n & 1)
        for (int w = t; w < CPC; w += TB) dst[npair * CPC + w] = src[(n - 1) * CPC + w];
}

__global__ void __launch_bounds__(TB) fused_kernel(const float* __restrict__ boxes,
                                                   const float* __restrict__ scores,
                                                   float* __restrict__ out) {
    extern __shared__ char smem_raw[];
    // NMS-phase layout (32 KB + 1 KB)
    float*  s_score = (float*)(smem_raw);                  // [1024]  @0
    int*    s_idx   = (int*)(smem_raw + 4096);             // [1024]  @4K
    float4* s_bx    = (float4*)(smem_raw + 8192);          // [1024]  @8K..24K
    float*  s_area  = (float*)(smem_raw + 24576);          // [1024]  @24K
    int*    s_keep  = (int*)(smem_raw + 28672);            // [1024]  @28K
    float*  rsum    = (float*)(smem_raw + 32768);          // [128]
    float*  rmax    = rsum + 128;                          // [128]
    __shared__ float wsum[TB / 32], wmax[TB / 32];
    __shared__ int s_cnt;

    int t = threadIdx.x;
    int b = blockIdx.x;   // == class id for phase 3

    // ---- Phase 1: partial mean/max over fg slice (1000 elems/block) ----
    float psum = 0.f, pmax = -INFINITY;
    for (int j = t; j < (R_N * K_N) / K_N; j += TB) {   // 1000 per block
        int idx = b * 1000 + j;
        int r = idx / K_N;
        int c = idx - r * K_N;
        float v = __ldg(scores + r * NCLS_P1 + c);
        psum += v;
        pmax = fmaxf(pmax, v);
    }
    #pragma unroll
    for (int o = 16; o; o >>= 1) {
        psum += __shfl_xor_sync(0xffffffffu, psum, o);
        pmax = fmaxf(pmax, __shfl_xor_sync(0xffffffffu, pmax, o));
    }
    if ((t & 31) == 0) { wsum[t >> 5] = psum; wmax[t >> 5] = pmax; }
    __syncthreads();
    if (t == 0) {
        float s = 0.f, m = -INFINITY;
        #pragma unroll
        for (int i = 0; i < TB / 32; i++) { s += wsum[i]; m = fmaxf(m, wmax[i]); }
        g_psum[b] = s; g_pmax[b] = m;
        __threadfence();
        atomicAdd(&g_bar1, 1);
        while (*(volatile int*)&g_bar1 < K_N) { }   // all 80 blocks resident: safe
        __threadfence();
    }
    __syncthreads();

    // ---- Phase 2: fold 80 partials (identical tree in every block) ----
    if (t < 128) {
        rsum[t] = (t < K_N) ? g_psum[t] : 0.f;
        rmax[t] = (t < K_N) ? g_pmax[t] : -INFINITY;
    }
    if (t == 0) s_cnt = 0;
    __syncthreads();
    #pragma unroll
    for (int s = 64; s > 0; s >>= 1) {
        if (t < s) { rsum[t] += rsum[t + s]; rmax[t] = fmaxf(rmax[t], rmax[t + s]); }
        __syncthreads();
    }
    float th = fminf(0.05f, 0.5f * (rsum[0] / (float)(R_N * K_N) + rmax[0]));

    // ---- Phase 3: per-class compact -> sort -> NMS -> emit top-100 ----
    for (int r = t; r < R_N; r += TB) {
        float s = __ldg(scores + r * NCLS_P1 + b);
        if (s > th) {
            int p = atomicAdd(&s_cnt, 1);
            s_score[p] = s;
            s_idx[p] = r;
        }
    }
    __syncthreads();
    int V = s_cnt;

    int P = 1;
    while (P < V) P <<= 1;
    for (int i = V + t; i < P; i += TB) {
        s_score[i] = -INFINITY;
        s_idx[i]   = R_N + i;
    }
    __syncthreads();

    // bitonic sort [0,P): score desc, tie -> index asc (total order, unique idx)
    for (int k = 2; k <= P; k <<= 1) {
        for (int j = k >> 1; j > 0; j >>= 1) {
            for (int i = t; i < P; i += TB) {
                int ixj = i ^ j;
                if (ixj > i) {
                    float s1 = s_score[i], s2 = s_score[ixj];
                    int   i1 = s_idx[i],   i2 = s_idx[ixj];
                    bool before2 = (s2 > s1) || (s2 == s1 && i2 < i1);
                    if (before2 == ((i & k) == 0)) {
                        s_score[i] = s2; s_score[ixj] = s1;
                        s_idx[i]   = i2; s_idx[ixj]   = i1;
                    }
                }
            }
            __syncthreads();
        }
    }

    for (int i = t; i < V; i += TB) {
        float4 bx = __ldg((const float4*)boxes + s_idx[i] * K_N + b);
        float x1 = fminf(fmaxf(bx.x, 0.f), IMG_W_F);
        float y1 = fminf(fmaxf(bx.y, 0.f), IMG_H_F);
        float x2 = fminf(fmaxf(bx.z, 0.f), IMG_W_F);
        float y2 = fminf(fmaxf(bx.w, 0.f), IMG_H_F);
        s_bx[i] = make_float4(x1, y1, x2, y2);
        s_area[i] = fmaxf(x2 - x1, 0.f) * fmaxf(y2 - y1, 0.f);
        s_keep[i] = 1;
    }
    __syncthreads();

    for (int i = 0; i < V; i++) {
        if (s_keep[i]) {
            float4 bi = s_bx[i];
            float  ai = s_area[i];
            for (int j = i + 1 + t; j < V; j += TB) {
                if (s_keep[j]) {
                    float4 bj = s_bx[j];
                    float xx1 = fmaxf(bi.x, bj.x);
                    float yy1 = fmaxf(bi.y, bj.y);
                    float xx2 = fminf(bi.z, bj.z);
                    float yy2 = fminf(bi.w, bj.w);
                    float inter = fmaxf(xx2 - xx1, 0.f) * fmaxf(yy2 - yy1, 0.f);
                    float uni = fmaxf(ai + s_area[j] - inter, 1e-9f);
                    if (inter > 0.5f * uni) s_keep[j] = 0;
                }
            }
        }
        __syncthreads();
    }

    // emit best 100 kept (sorted order) via warp-ballot ranking
    if (t < 32) {
        int base = b * CPC;
        int rank = 0;
        for (int s0 = 0; s0 < V; s0 += 32) {
            int i = s0 + t;
            int kp = (i < V) ? s_keep[i] : 0;
            unsigned m = __ballot_sync(0xffffffffu, kp);
            int myr = rank + __popc(m & ((1u << t) - 1u));
            if (kp && myr < CPC) {
                g_ord[base + myr]  = ord32(s_score[i]);
                g_prop[base + myr] = s_idx[i];
            }
            rank += __popc(m);
            if (rank >= CPC) break;
        }
        int kept = rank < CPC ? rank : CPC;
        for (int p = kept + t; p < CPC; p += 32) {
            g_ord[base + p] = 0u;
            g_prop[base + p] = 0;
        }
    }
    __syncthreads();

    // ---- barrier 2: only block 0 continues ----
    if (t == 0) { __threadfence(); atomicAdd(&g_bar2, 1); }
    if (b != 0) return;
    if (t == 0) {
        while (*(volatile int*)&g_bar2 < K_N) { }
        __threadfence();
    }
    __syncthreads();

    // ---- Phase 4 (block 0): tournament merge 80 -> 1, then output ----
    u32* ordsh = (u32*)(smem_raw);            // 8000 u32 = 32 KB
    u64* A     = (u64*)(smem_raw + 32768);    // 4000 u64 = 32 KB
    u64* B     = (u64*)(smem_raw + 65536);    // 2000 u64 = 16 KB
    for (int i = t; i < K_N * CPC; i += TB) ordsh[i] = g_ord[i];
    __syncthreads();

    // level 0: 80 -> 40, keys built on the fly from u32 ord
    for (int w = t; w < 40 * (2 * CPC); w += TB) {
        int p = w / (2 * CPC), e = w - p * (2 * CPC);
        int c0 = 2 * p, c1 = 2 * p + 1;
        int c, k, oc;
        if (e < CPC) { c = c0; k = e;       oc = c1; }
        else         { c = c1; k = e - CPC; oc = c0; }
        u64 v = mkkey(ordsh[c * CPC + k], c, k);
        int lo = 0, hi = CPC;
        while (lo < hi) {
            int mid = (lo + hi) >> 1;
            if (mkkey(ordsh[oc * CPC + mid], oc, mid) > v) lo = mid + 1; else hi = mid;
        }
        int pos = k + lo;
        if (pos < CPC) A[p * CPC + pos] = v;
    }
    __syncthreads();

    merge_lists(A, B, 40, t); __syncthreads();   // 40 -> 20
    merge_lists(B, A, 20, t); __syncthreads();   // 20 -> 10
    merge_lists(A, B, 10, t); __syncthreads();   // 10 -> 5
    merge_lists(B, A, 5, t);  __syncthreads();   // 5  -> 3
    merge_lists(A, B, 3, t);  __syncthreads();   // 3  -> 2
    merge_lists(B, A, 2, t);  __syncthreads();   // 2  -> 1 (result A[0..99])

    // Output: [100, 87] = box(4) | score | class | full_scores(81)
    for (int e = t; e < CPC * OUT_COLS; e += TB) {
        int row = e / OUT_COLS;
        int col = e - row * OUT_COLS;
        u64 key = A[row];
        u32 o = (u32)(key >> 32);
        float val = 0.f;
        if (o != 0u) {
            int c = (K_N - 1) - (int)((key >> 7) & 127u);
            int k = (CPC - 1) - (int)(key & 127u);
            int prop = g_prop[c * CPC + k];
            if (col < 4) {
                float bv = __ldg(boxes + prop * (K_N * 4) + c * 4 + col);
                float lim = (col & 1) ? IMG_H_F : IMG_W_F;
                val = fminf(fmaxf(bv, 0.f), lim);
            } else if (col == 4) {
                val = __uint_as_float(o & 0x7FFFFFFFu);
            } else if (col == 5) {
                val = (float)c;
            } else {
                val = __ldg(scores + prop * NCLS_P1 + (col - 6));
            }
        }
        out[e] = val;
    }
    __syncthreads();

    // reset grid barriers for the next graph replay
    if (t == 0) { g_bar1 = 0; g_bar2 = 0; }
}

// ---------------------------------------------------------------------------
extern "C" void kernel_launch(void* const* d_in, const int* in_sizes, int n_in,
                              void* d_out, int out_size) {
    const float* boxes  = (const float*)d_in[0];
    const float* scores = (const float*)d_in[1];
    if (in_sizes[0] != R_N * K_N * 4) {
        boxes  = (const float*)d_in[1];
        scores = (const float*)d_in[0];
    }
    static const int DYN_SMEM = 81920;   // max(NMS 33.8KB, topk 80KB)
    cudaFuncSetAttribute(fused_kernel, cudaFuncAttributeMaxDynamicSharedMemorySize, DYN_SMEM);
    fused_kernel<<<K_N, TB, DYN_SMEM>>>(boxes, scores, (float*)d_out);
}